// round 6
// baseline (speedup 1.0000x reference)
#include <cuda_runtime.h>

#define NNODE  128
#define NEDGE  1024
#define ETOT   1152
#define HFEAT  128
#define NGRAPH 1024
#define NTHREADS 512

// ---------------------------------------------------------------------------
// Device-global CSR (edge template shared by all graphs).
// ---------------------------------------------------------------------------
__device__ int g_csr_ptr[NNODE + 1];
__device__ int g_csr_src[ETOT];

__global__ void build_csr_kernel(const int* __restrict__ ei) {
    __shared__ int s_src[NEDGE];
    __shared__ int s_dst[NEDGE];
    __shared__ int cnt[NNODE];
    __shared__ int base[NNODE + 1];
    int t = threadIdx.x;
    if (t < NEDGE) { s_src[t] = ei[t]; s_dst[t] = ei[NEDGE + t]; }
    if (t < NNODE) cnt[t] = 0;
    __syncthreads();
    if (t < NEDGE) atomicAdd(&cnt[s_dst[t]], 1);
    __syncthreads();
    if (t == 0) {
        int acc = 0;
        for (int d = 0; d < NNODE; ++d) { base[d] = acc; acc += cnt[d] + 1; }
        base[NNODE] = acc;
    }
    __syncthreads();
    if (t <= NNODE) g_csr_ptr[t] = base[t];
    if (t < NEDGE) {
        int d = s_dst[t];
        int rank = 0;
        for (int e = 0; e < t; ++e) rank += (s_dst[e] == d) ? 1 : 0;
        g_csr_src[base[d] + rank] = s_src[t];
    }
    if (t < NNODE) g_csr_src[base[t] + cnt[t]] = t;  // self loop last
}

// ---------------------------------------------------------------------------
// Shared memory layout (pitch 128; all hot phases access rows contiguously)
// ---------------------------------------------------------------------------
constexpr int OFF_SH    = 0;
constexpr int OFF_SXH   = OFF_SH  + NNODE * HFEAT;       // 16384
constexpr int OFF_SW    = OFF_SXH + NNODE * HFEAT;       // 16384 (sex overlaid)
constexpr int OFF_SS    = OFF_SW  + HFEAT * HFEAT;
constexpr int OFF_SD    = OFF_SS  + 512;
constexpr int OFF_RINV  = OFF_SD  + 512;
constexpr int OFF_SATT  = OFF_RINV + 512;
constexpr int OFF_SCALE = OFF_SATT + 256;
constexpr int OFF_BIAS  = OFF_SCALE + 128;
constexpr int OFF_POOL  = OFF_BIAS + 128;
constexpr int OFF_HP    = OFF_POOL + 512;
constexpr int OFF_ZZ    = OFF_HP + 128;
constexpr int SM_FLOATS = OFF_ZZ + 64;
constexpr int SM_INTS   = 132 + ETOT;
constexpr int SMEM_BYTES = SM_FLOATS * 4 + SM_INTS * 4;   // ~213 KB

// ---------------------------------------------------------------------------
// Packed fp32x2 helpers (FFMA2 is PTX-only)
// ---------------------------------------------------------------------------
__device__ __forceinline__ unsigned long long pack2(float a) {
    unsigned long long r;
    unsigned int ai = __float_as_uint(a);
    asm("mov.b64 %0, {%1, %1};" : "=l"(r) : "r"(ai));
    return r;
}
__device__ __forceinline__ void ffma2(unsigned long long& d,
                                      unsigned long long a,
                                      unsigned long long b) {
    asm("fma.rn.f32x2 %0, %1, %2, %0;" : "+l"(d) : "l"(a), "l"(b));
}

// ---------------------------------------------------------------------------
// C[128,128] = A[128,128] @ W[128,128], all SMEM (pitch 128). ALL 16 warps.
// Warp tile: 8 rows x 128 cols; thread tile 4 x 8.
//  - A: LDS.64, 2 distinct addresses/warp (broadcast dedup)
//  - W: LDS.128, lanes 0-15 contiguous 16B chunks (dup lanes 16-31 dedup)
// Caller syncs around it.
// ---------------------------------------------------------------------------
__device__ __forceinline__ void gemm16(const float* __restrict__ A,
                                       const float* __restrict__ sW,
                                       float* __restrict__ C, int tid) {
    const int w  = tid >> 5;
    const int l  = tid & 31;
    const int r0 = w * 8 + (l >> 4) * 4;
    const int ca = (l & 15) * 8;

    unsigned long long acc[4][4];
#pragma unroll
    for (int i = 0; i < 4; ++i)
#pragma unroll
        for (int j = 0; j < 4; ++j) acc[i][j] = 0ull;

#pragma unroll 4
    for (int k = 0; k < HFEAT; k += 2) {
        float2 a[4];
#pragma unroll
        for (int i = 0; i < 4; ++i)
            a[i] = *(const float2*)(A + (r0 + i) * HFEAT + k);
        ulonglong2 w00 = *(const ulonglong2*)(sW + k * HFEAT + ca);
        ulonglong2 w01 = *(const ulonglong2*)(sW + k * HFEAT + ca + 4);
        ulonglong2 w10 = *(const ulonglong2*)(sW + (k + 1) * HFEAT + ca);
        ulonglong2 w11 = *(const ulonglong2*)(sW + (k + 1) * HFEAT + ca + 4);
#pragma unroll
        for (int i = 0; i < 4; ++i) {
            unsigned long long ax = pack2(a[i].x);
            unsigned long long ay = pack2(a[i].y);
            ffma2(acc[i][0], ax, w00.x);
            ffma2(acc[i][1], ax, w00.y);
            ffma2(acc[i][2], ax, w01.x);
            ffma2(acc[i][3], ax, w01.y);
            ffma2(acc[i][0], ay, w10.x);
            ffma2(acc[i][1], ay, w10.y);
            ffma2(acc[i][2], ay, w11.x);
            ffma2(acc[i][3], ay, w11.y);
        }
    }
#pragma unroll
    for (int i = 0; i < 4; ++i) {
        ulonglong2 s0, s1;
        s0.x = acc[i][0]; s0.y = acc[i][1];
        s1.x = acc[i][2]; s1.y = acc[i][3];
        *(ulonglong2*)(C + (r0 + i) * HFEAT + ca)     = s0;
        *(ulonglong2*)(C + (r0 + i) * HFEAT + ca + 4) = s1;
    }
}

__global__ __launch_bounds__(NTHREADS, 1)
void gnn_kernel(const float* __restrict__ x,
                const float* __restrict__ w_in, const float* __restrict__ b_in,
                const float* __restrict__ g0w, const float* __restrict__ g0as,
                const float* __restrict__ g0ad, const float* __restrict__ g0b,
                const float* __restrict__ bn0g, const float* __restrict__ bn0b,
                const float* __restrict__ bn0m, const float* __restrict__ bn0v,
                const float* __restrict__ g1w, const float* __restrict__ g1as,
                const float* __restrict__ g1ad, const float* __restrict__ g1b,
                const float* __restrict__ bn1g, const float* __restrict__ bn1b,
                const float* __restrict__ bn1m, const float* __restrict__ bn1v,
                const float* __restrict__ w1, const float* __restrict__ b1,
                const float* __restrict__ w2, const float* __restrict__ b2,
                float* __restrict__ out) {
    extern __shared__ float smem[];
    float* sh    = smem + OFF_SH;
    float* sxh   = smem + OFF_SXH;
    float* sW    = smem + OFF_SW;
    float* sex   = smem + OFF_SW;     // overlaid: disjoint lifetime vs W use
    float* s_s   = smem + OFF_SS;
    float* s_d   = smem + OFF_SD;
    float* rinv  = smem + OFF_RINV;
    float* satt  = smem + OFF_SATT;
    float* sscale= smem + OFF_SCALE;
    float* sbias = smem + OFF_BIAS;
    float* pool  = smem + OFF_POOL;
    float* hp    = smem + OFF_HP;
    float* zz    = smem + OFF_ZZ;
    int*   sptr  = (int*)(smem + SM_FLOATS);
    int*   scsr  = sptr + 132;

    const int tid  = threadIdx.x;
    const int wid  = tid >> 5;
    const int lane = tid & 31;
    const int b    = blockIdx.x;

    // stage CSR
    for (int i = tid; i <= NNODE; i += NTHREADS) sptr[i] = g_csr_ptr[i];
    for (int i = tid; i < ETOT; i += NTHREADS)   scsr[i] = g_csr_src[i];

    // stage W0 (resident), attention vecs, BN0 fold
    for (int i = tid; i < HFEAT * HFEAT / 4; i += NTHREADS)
        *(float4*)(sW + i * 4) = *(const float4*)(g0w + i * 4);
    if (tid < 128) {
        satt[tid]       = g0as[tid];
        satt[128 + tid] = g0ad[tid];
        float sc = bn0g[tid] * rsqrtf(bn0v[tid] + 1e-5f);
        sscale[tid] = sc;
        sbias[tid]  = fmaf(g0b[tid] - bn0m[tid], sc, bn0b[tid]);
    }

    // input projection: h = relu(x_n * w_in + b_in)
    const float* xr = x + b * NNODE;
    for (int it = tid; it < NNODE * 32; it += NTHREADS) {
        int n = it >> 5, fq = it & 31;
        float xv = xr[n];
        float4 w  = *(const float4*)(w_in + fq * 4);
        float4 bb = *(const float4*)(b_in + fq * 4);
        float4 r;
        r.x = fmaxf(fmaf(xv, w.x, bb.x), 0.0f);
        r.y = fmaxf(fmaf(xv, w.y, bb.y), 0.0f);
        r.z = fmaxf(fmaf(xv, w.z, bb.z), 0.0f);
        r.w = fmaxf(fmaf(xv, w.w, bb.w), 0.0f);
        *(float4*)(sh + n * HFEAT + fq * 4) = r;
    }
    __syncthreads();

    // ==================== GAT layer 0 ====================
    gemm16(sh, sW, sxh, tid);
    __syncthreads();

    // scores: warp per node, per-head 8-lane shuffle reduce (conflict-free)
    {
        float4 a1 = *(const float4*)(satt + lane * 4);        // a_s (head = lane>>3)
        float4 a2 = *(const float4*)(satt + 128 + lane * 4);  // a_d
        for (int n = wid; n < NNODE; n += 16) {
            float4 v = *(const float4*)(sxh + n * HFEAT + lane * 4);
            float ss = v.x*a1.x + v.y*a1.y + v.z*a1.z + v.w*a1.w;
            float dd = v.x*a2.x + v.y*a2.y + v.z*a2.z + v.w*a2.w;
#pragma unroll
            for (int o = 4; o; o >>= 1) {
                ss += __shfl_xor_sync(0xffffffffu, ss, o);
                dd += __shfl_xor_sync(0xffffffffu, dd, o);
            }
            if ((lane & 7) == 0) {
                s_s[n * 4 + (lane >> 3)] = ss;
                s_d[n * 4 + (lane >> 3)] = dd;
            }
        }
    }
    __syncthreads();   // ends all sW(g0w) reads: sex may now be written

    // softmax per (dst, head): pass1 caches leaky(e), pass2 exps
    {
        int d  = tid & 127;
        int hh = tid >> 7;
        int beg = sptr[d], end = sptr[d + 1];
        float sd = s_d[d * 4 + hh];
        float mx = -1e30f;
        for (int p = beg; p < end; ++p) {
            float e = s_s[scsr[p] * 4 + hh] + sd;
            e = (e > 0.0f) ? e : 0.2f * e;
            sex[p * 4 + hh] = e;
            mx = fmaxf(mx, e);
        }
        float sum = 0.0f;
        for (int p = beg; p < end; ++p) {
            float ex = __expf(sex[p * 4 + hh] - mx);
            sex[p * 4 + hh] = ex;
            sum += ex;
        }
        rinv[d * 4 + hh] = 1.0f / sum;
    }
    __syncthreads();

    // aggregate + BN0 + relu (warp-per-node, float4 per lane) -> sh
    {
        int hh = lane >> 3;
        float4 sc = *(const float4*)(sscale + lane * 4);
        float4 bs = *(const float4*)(sbias + lane * 4);
        for (int d = wid; d < NNODE; d += 16) {
            int beg = sptr[d], end = sptr[d + 1];
            float rv = rinv[d * 4 + hh];
            float4 acc = make_float4(0.f, 0.f, 0.f, 0.f);
            for (int p = beg; p < end; ++p) {
                float w = sex[p * 4 + hh];
                const float4 v = *(const float4*)(sxh + scsr[p] * HFEAT + lane * 4);
                acc.x = fmaf(w, v.x, acc.x);
                acc.y = fmaf(w, v.y, acc.y);
                acc.z = fmaf(w, v.z, acc.z);
                acc.w = fmaf(w, v.w, acc.w);
            }
            float4 r;
            r.x = fmaxf(fmaf(acc.x * rv, sc.x, bs.x), 0.0f);
            r.y = fmaxf(fmaf(acc.y * rv, sc.y, bs.y), 0.0f);
            r.z = fmaxf(fmaf(acc.z * rv, sc.z, bs.z), 0.0f);
            r.w = fmaxf(fmaf(acc.w * rv, sc.w, bs.w), 0.0f);
            *(float4*)(sh + d * HFEAT + lane * 4) = r;
        }
    }
    __syncthreads();   // sex reads done -> sW region reusable

    // stage W1 over sex/sW + layer-1 attention + BN1 fold
    for (int i = tid; i < HFEAT * HFEAT / 4; i += NTHREADS)
        *(float4*)(sW + i * 4) = *(const float4*)(g1w + i * 4);
    if (tid < 128) {
        float sc = bn1g[tid] * rsqrtf(bn1v[tid] + 1e-5f);
        sscale[tid] = sc;
        sbias[tid]  = fmaf(g1b[tid] - bn1m[tid], sc, bn1b[tid]);
        satt[tid]       = g1as[tid];
        satt[128 + tid] = g1ad[tid];
    }
    __syncthreads();

    // ==================== GAT layer 1 ====================
    gemm16(sh, sW, sxh, tid);
    __syncthreads();

    // scores: warp per node, full 32-lane reduce
    {
        float4 a1 = *(const float4*)(satt + lane * 4);
        float4 a2 = *(const float4*)(satt + 128 + lane * 4);
        for (int nd = wid; nd < NNODE; nd += 16) {
            float4 v = *(const float4*)(sxh + nd * HFEAT + lane * 4);
            float ss = v.x*a1.x + v.y*a1.y + v.z*a1.z + v.w*a1.w;
            float dd = v.x*a2.x + v.y*a2.y + v.z*a2.z + v.w*a2.w;
#pragma unroll
            for (int o = 16; o; o >>= 1) {
                ss += __shfl_xor_sync(0xffffffffu, ss, o);
                dd += __shfl_xor_sync(0xffffffffu, dd, o);
            }
            if (lane == 0) { s_s[nd] = ss; s_d[nd] = dd; }
        }
    }
    __syncthreads();   // ends sW(g1w) reads -> sex writable

    if (tid < 128) {
        int d = tid;
        int beg = sptr[d], end = sptr[d + 1];
        float sd = s_d[d];
        float mx = -1e30f;
        for (int p = beg; p < end; ++p) {
            float e = s_s[scsr[p]] + sd;
            e = (e > 0.0f) ? e : 0.2f * e;
            sex[p] = e;
            mx = fmaxf(mx, e);
        }
        float sum = 0.0f;
        for (int p = beg; p < end; ++p) {
            float ex = __expf(sex[p] - mx);
            sex[p] = ex;
            sum += ex;
        }
        rinv[d] = 1.0f / sum;
    }
    __syncthreads();

    // aggregate + BN1 + relu -> sh
    {
        float4 sc = *(const float4*)(sscale + lane * 4);
        float4 bs = *(const float4*)(sbias + lane * 4);
        for (int d = wid; d < NNODE; d += 16) {
            int beg = sptr[d], end = sptr[d + 1];
            float rv = rinv[d];
            float4 acc = make_float4(0.f, 0.f, 0.f, 0.f);
            for (int p = beg; p < end; ++p) {
                float w = sex[p];
                const float4 v = *(const float4*)(sxh + scsr[p] * HFEAT + lane * 4);
                acc.x = fmaf(w, v.x, acc.x);
                acc.y = fmaf(w, v.y, acc.y);
                acc.z = fmaf(w, v.z, acc.z);
                acc.w = fmaf(w, v.w, acc.w);
            }
            float4 r;
            r.x = fmaxf(fmaf(acc.x * rv, sc.x, bs.x), 0.0f);
            r.y = fmaxf(fmaf(acc.y * rv, sc.y, bs.y), 0.0f);
            r.z = fmaxf(fmaf(acc.z * rv, sc.z, bs.z), 0.0f);
            r.w = fmaxf(fmaf(acc.w * rv, sc.w, bs.w), 0.0f);
            *(float4*)(sh + d * HFEAT + lane * 4) = r;
        }
    }
    __syncthreads();

    // -------- mean pool --------
    {
        int g = tid >> 7, f = tid & 127;
        float acc = 0.0f;
#pragma unroll 4
        for (int n = g * 32; n < g * 32 + 32; ++n) acc += sh[n * HFEAT + f];
        pool[g * 128 + f] = acc;
    }
    __syncthreads();
    if (tid < 128)
        hp[tid] = (pool[tid] + pool[128 + tid] + pool[256 + tid] + pool[384 + tid])
                  * (1.0f / 128.0f);
    __syncthreads();

    // -------- MLP --------
    if (tid < 64) {
        float acc = b1[tid];
#pragma unroll 8
        for (int f = 0; f < 128; ++f) acc = fmaf(hp[f], w1[f * 64 + tid], acc);
        zz[tid] = fmaxf(acc, 0.0f);
    }
    __syncthreads();
    if (tid == 0) {
        float acc = b2[0];
#pragma unroll
        for (int j = 0; j < 64; ++j) acc = fmaf(zz[j], w2[j], acc);
        out[b] = acc;
    }
}

// ---------------------------------------------------------------------------
extern "C" void kernel_launch(void* const* d_in, const int* in_sizes, int n_in,
                              void* d_out, int out_size) {
    (void)in_sizes; (void)n_in; (void)out_size;
    const float* x    = (const float*)d_in[0];
    const int*   ei   = (const int*)d_in[1];
    const float* w_in = (const float*)d_in[2];
    const float* b_in = (const float*)d_in[3];
    const float* g0w  = (const float*)d_in[4];
    const float* g0as = (const float*)d_in[5];
    const float* g0ad = (const float*)d_in[6];
    const float* g0b  = (const float*)d_in[7];
    const float* bn0g = (const float*)d_in[8];
    const float* bn0b = (const float*)d_in[9];
    const float* bn0m = (const float*)d_in[10];
    const float* bn0v = (const float*)d_in[11];
    const float* g1w  = (const float*)d_in[12];
    const float* g1as = (const float*)d_in[13];
    const float* g1ad = (const float*)d_in[14];
    const float* g1b  = (const float*)d_in[15];
    const float* bn1g = (const float*)d_in[16];
    const float* bn1b = (const float*)d_in[17];
    const float* bn1m = (const float*)d_in[18];
    const float* bn1v = (const float*)d_in[19];
    const float* w1   = (const float*)d_in[20];
    const float* b1   = (const float*)d_in[21];
    const float* w2   = (const float*)d_in[22];
    const float* b2   = (const float*)d_in[23];
    float* out = (float*)d_out;

    cudaFuncSetAttribute(gnn_kernel,
                         cudaFuncAttributeMaxDynamicSharedMemorySize, SMEM_BYTES);

    build_csr_kernel<<<1, 1024>>>(ei);
    gnn_kernel<<<NGRAPH, NTHREADS, SMEM_BYTES>>>(
        x, w_in, b_in,
        g0w, g0as, g0ad, g0b, bn0g, bn0b, bn0m, bn0v,
        g1w, g1as, g1ad, g1b, bn1g, bn1b, bn1m, bn1v,
        w1, b1, w2, b2, out);
}

// round 7
// speedup vs baseline: 1.2584x; 1.2584x over previous
#include <cuda_runtime.h>

#define NNODE  128
#define NEDGE  1024
#define ETOT   1152
#define HFEAT  128
#define NGRAPH 1024
#define NTHREADS 512

// ---------------------------------------------------------------------------
// Device-global CSR (edge template shared by all graphs).
// ---------------------------------------------------------------------------
__device__ int g_csr_ptr[NNODE + 1];
__device__ int g_csr_src[ETOT];

__global__ void build_csr_kernel(const int* __restrict__ ei) {
    __shared__ int s_src[NEDGE];
    __shared__ int s_dst[NEDGE];
    __shared__ int cnt[NNODE];
    __shared__ int base[NNODE + 1];
    int t = threadIdx.x;
    if (t < NEDGE) { s_src[t] = ei[t]; s_dst[t] = ei[NEDGE + t]; }
    if (t < NNODE) cnt[t] = 0;
    __syncthreads();
    if (t < NEDGE) atomicAdd(&cnt[s_dst[t]], 1);
    __syncthreads();
    if (t == 0) {
        int acc = 0;
        for (int d = 0; d < NNODE; ++d) { base[d] = acc; acc += cnt[d] + 1; }
        base[NNODE] = acc;
    }
    __syncthreads();
    if (t <= NNODE) g_csr_ptr[t] = base[t];
    if (t < NEDGE) {
        int d = s_dst[t];
        int rank = 0;
        for (int e = 0; e < t; ++e) rank += (s_dst[e] == d) ? 1 : 0;
        g_csr_src[base[d] + rank] = s_src[t];
    }
    if (t < NNODE) g_csr_src[base[t] + cnt[t]] = t;  // self loop last
}

// ---------------------------------------------------------------------------
// Shared memory layout (pitch 128)
// ---------------------------------------------------------------------------
constexpr int OFF_SH    = 0;
constexpr int OFF_SXH   = OFF_SH  + NNODE * HFEAT;       // 16384
constexpr int OFF_SW    = OFF_SXH + NNODE * HFEAT;       // 16384 (sex overlaid)
constexpr int OFF_SS    = OFF_SW  + HFEAT * HFEAT;
constexpr int OFF_SD    = OFF_SS  + 512;
constexpr int OFF_RINV  = OFF_SD  + 512;
constexpr int OFF_SATT  = OFF_RINV + 512;
constexpr int OFF_SCALE = OFF_SATT + 256;
constexpr int OFF_BIAS  = OFF_SCALE + 128;
constexpr int OFF_POOL  = OFF_BIAS + 128;
constexpr int OFF_HP    = OFF_POOL + 512;
constexpr int OFF_ZZ    = OFF_HP + 128;
constexpr int SM_FLOATS = OFF_ZZ + 64;
constexpr int SM_INTS   = 132 + ETOT;
constexpr int SMEM_BYTES = SM_FLOATS * 4 + SM_INTS * 4;   // ~213 KB

// ---------------------------------------------------------------------------
// Packed fp32x2 helpers (f32x2 ops are PTX-only)
// ---------------------------------------------------------------------------
__device__ __forceinline__ unsigned long long pack2(float a) {
    unsigned long long r;
    unsigned int ai = __float_as_uint(a);
    asm("mov.b64 %0, {%1, %1};" : "=l"(r) : "r"(ai));
    return r;
}
__device__ __forceinline__ void ffma2(unsigned long long& d,
                                      unsigned long long a,
                                      unsigned long long b) {
    asm("fma.rn.f32x2 %0, %1, %2, %0;" : "+l"(d) : "l"(a), "l"(b));
}
__device__ __forceinline__ void fadd2(unsigned long long& d,
                                      unsigned long long a) {
    asm("add.rn.f32x2 %0, %0, %1;" : "+l"(d) : "l"(a));
}

// ---------------------------------------------------------------------------
// Split-K GEMM: C[128,128] = A[128,128] @ W[128,128], all SMEM (pitch 128).
// ALL 16 warps, thread tile 8x8 (1 B/MAC per thread — the R4 optimum).
// Warps 0-7: rows (w&7)*16..+16, k in [0,64).  Warps 8-15: same rows, k in
// [64,128).  kh=1 warps store partials to C; after barrier kh=0 warps
// add their half (add.rn.f32x2) and store the final sum.
// Contains ONE internal __syncthreads(); all 512 threads must call.
// ---------------------------------------------------------------------------
__device__ __forceinline__ void gemm_sk(const float* __restrict__ A,
                                        const float* __restrict__ sW,
                                        float* __restrict__ C, int tid) {
    const int w  = tid >> 5;
    const int l  = tid & 31;
    const int kh = w >> 3;                 // k half
    const int r0 = (w & 7) * 16 + (l >> 4) * 8;
    const int ca = (l & 15) * 4;           // cols [ca,ca+4) and [ca+64,ca+68)
    const int k0 = kh * 64;

    unsigned long long acc[8][4];
#pragma unroll
    for (int i = 0; i < 8; ++i)
#pragma unroll
        for (int j = 0; j < 4; ++j) acc[i][j] = 0ull;

#pragma unroll 2
    for (int k = k0; k < k0 + 64; k += 2) {
        float2 a[8];
#pragma unroll
        for (int i = 0; i < 8; ++i)
            a[i] = *(const float2*)(A + (r0 + i) * HFEAT + k);
        ulonglong2 w00 = *(const ulonglong2*)(sW + k * HFEAT + ca);
        ulonglong2 w01 = *(const ulonglong2*)(sW + k * HFEAT + ca + 64);
        ulonglong2 w10 = *(const ulonglong2*)(sW + (k + 1) * HFEAT + ca);
        ulonglong2 w11 = *(const ulonglong2*)(sW + (k + 1) * HFEAT + ca + 64);
#pragma unroll
        for (int i = 0; i < 8; ++i) {
            unsigned long long ax = pack2(a[i].x);
            unsigned long long ay = pack2(a[i].y);
            ffma2(acc[i][0], ax, w00.x);
            ffma2(acc[i][1], ax, w00.y);
            ffma2(acc[i][2], ax, w01.x);
            ffma2(acc[i][3], ax, w01.y);
            ffma2(acc[i][0], ay, w10.x);
            ffma2(acc[i][1], ay, w10.y);
            ffma2(acc[i][2], ay, w11.x);
            ffma2(acc[i][3], ay, w11.y);
        }
    }

    if (kh == 1) {
#pragma unroll
        for (int i = 0; i < 8; ++i) {
            ulonglong2 s0, s1;
            s0.x = acc[i][0]; s0.y = acc[i][1];
            s1.x = acc[i][2]; s1.y = acc[i][3];
            *(ulonglong2*)(C + (r0 + i) * HFEAT + ca)      = s0;
            *(ulonglong2*)(C + (r0 + i) * HFEAT + ca + 64) = s1;
        }
    }
    __syncthreads();
    if (kh == 0) {
#pragma unroll
        for (int i = 0; i < 8; ++i) {
            ulonglong2 p0 = *(const ulonglong2*)(C + (r0 + i) * HFEAT + ca);
            ulonglong2 p1 = *(const ulonglong2*)(C + (r0 + i) * HFEAT + ca + 64);
            fadd2(acc[i][0], p0.x);
            fadd2(acc[i][1], p0.y);
            fadd2(acc[i][2], p1.x);
            fadd2(acc[i][3], p1.y);
            ulonglong2 s0, s1;
            s0.x = acc[i][0]; s0.y = acc[i][1];
            s1.x = acc[i][2]; s1.y = acc[i][3];
            *(ulonglong2*)(C + (r0 + i) * HFEAT + ca)      = s0;
            *(ulonglong2*)(C + (r0 + i) * HFEAT + ca + 64) = s1;
        }
    }
}

__global__ __launch_bounds__(NTHREADS, 1)
void gnn_kernel(const float* __restrict__ x,
                const float* __restrict__ w_in, const float* __restrict__ b_in,
                const float* __restrict__ g0w, const float* __restrict__ g0as,
                const float* __restrict__ g0ad, const float* __restrict__ g0b,
                const float* __restrict__ bn0g, const float* __restrict__ bn0b,
                const float* __restrict__ bn0m, const float* __restrict__ bn0v,
                const float* __restrict__ g1w, const float* __restrict__ g1as,
                const float* __restrict__ g1ad, const float* __restrict__ g1b,
                const float* __restrict__ bn1g, const float* __restrict__ bn1b,
                const float* __restrict__ bn1m, const float* __restrict__ bn1v,
                const float* __restrict__ w1, const float* __restrict__ b1,
                const float* __restrict__ w2, const float* __restrict__ b2,
                float* __restrict__ out) {
    extern __shared__ float smem[];
    float* sh    = smem + OFF_SH;
    float* sxh   = smem + OFF_SXH;
    float* sW    = smem + OFF_SW;
    float* sex   = smem + OFF_SW;     // overlaid: disjoint lifetime vs W use
    float* s_s   = smem + OFF_SS;
    float* s_d   = smem + OFF_SD;
    float* rinv  = smem + OFF_RINV;
    float* satt  = smem + OFF_SATT;
    float* sscale= smem + OFF_SCALE;
    float* sbias = smem + OFF_BIAS;
    float* pool  = smem + OFF_POOL;
    float* hp    = smem + OFF_HP;
    float* zz    = smem + OFF_ZZ;
    int*   sptr  = (int*)(smem + SM_FLOATS);
    int*   scsr  = sptr + 132;

    const int tid  = threadIdx.x;
    const int wid  = tid >> 5;
    const int lane = tid & 31;
    const int b    = blockIdx.x;

    // stage CSR
    for (int i = tid; i <= NNODE; i += NTHREADS) sptr[i] = g_csr_ptr[i];
    for (int i = tid; i < ETOT; i += NTHREADS)   scsr[i] = g_csr_src[i];

    // stage W0 (resident), attention vecs, BN0 fold
    for (int i = tid; i < HFEAT * HFEAT / 4; i += NTHREADS)
        *(float4*)(sW + i * 4) = *(const float4*)(g0w + i * 4);
    if (tid < 128) {
        satt[tid]       = g0as[tid];
        satt[128 + tid] = g0ad[tid];
        float sc = bn0g[tid] * rsqrtf(bn0v[tid] + 1e-5f);
        sscale[tid] = sc;
        sbias[tid]  = fmaf(g0b[tid] - bn0m[tid], sc, bn0b[tid]);
    }

    // input projection: h = relu(x_n * w_in + b_in)
    const float* xr = x + b * NNODE;
    for (int it = tid; it < NNODE * 32; it += NTHREADS) {
        int n = it >> 5, fq = it & 31;
        float xv = xr[n];
        float4 w  = *(const float4*)(w_in + fq * 4);
        float4 bb = *(const float4*)(b_in + fq * 4);
        float4 r;
        r.x = fmaxf(fmaf(xv, w.x, bb.x), 0.0f);
        r.y = fmaxf(fmaf(xv, w.y, bb.y), 0.0f);
        r.z = fmaxf(fmaf(xv, w.z, bb.z), 0.0f);
        r.w = fmaxf(fmaf(xv, w.w, bb.w), 0.0f);
        *(float4*)(sh + n * HFEAT + fq * 4) = r;
    }
    __syncthreads();

    // ==================== GAT layer 0 ====================
    gemm_sk(sh, sW, sxh, tid);
    __syncthreads();

    // scores: warp per node, per-head 8-lane shuffle reduce (conflict-free)
    {
        float4 a1 = *(const float4*)(satt + lane * 4);        // a_s (head = lane>>3)
        float4 a2 = *(const float4*)(satt + 128 + lane * 4);  // a_d
        for (int n = wid; n < NNODE; n += 16) {
            float4 v = *(const float4*)(sxh + n * HFEAT + lane * 4);
            float ss = v.x*a1.x + v.y*a1.y + v.z*a1.z + v.w*a1.w;
            float dd = v.x*a2.x + v.y*a2.y + v.z*a2.z + v.w*a2.w;
#pragma unroll
            for (int o = 4; o; o >>= 1) {
                ss += __shfl_xor_sync(0xffffffffu, ss, o);
                dd += __shfl_xor_sync(0xffffffffu, dd, o);
            }
            if ((lane & 7) == 0) {
                s_s[n * 4 + (lane >> 3)] = ss;
                s_d[n * 4 + (lane >> 3)] = dd;
            }
        }
    }
    __syncthreads();   // ends all sW(g0w) reads: sex may now be written

    // softmax per (dst, head): pass1 caches leaky(e), pass2 exps
    {
        int d  = tid & 127;
        int hh = tid >> 7;
        int beg = sptr[d], end = sptr[d + 1];
        float sd = s_d[d * 4 + hh];
        float mx = -1e30f;
        for (int p = beg; p < end; ++p) {
            float e = s_s[scsr[p] * 4 + hh] + sd;
            e = (e > 0.0f) ? e : 0.2f * e;
            sex[p * 4 + hh] = e;
            mx = fmaxf(mx, e);
        }
        float sum = 0.0f;
        for (int p = beg; p < end; ++p) {
            float ex = __expf(sex[p * 4 + hh] - mx);
            sex[p * 4 + hh] = ex;
            sum += ex;
        }
        rinv[d * 4 + hh] = 1.0f / sum;
    }
    __syncthreads();

    // aggregate + BN0 + relu (warp-per-node, float4 per lane) -> sh
    {
        int hh = lane >> 3;
        float4 sc = *(const float4*)(sscale + lane * 4);
        float4 bs = *(const float4*)(sbias + lane * 4);
        for (int d = wid; d < NNODE; d += 16) {
            int beg = sptr[d], end = sptr[d + 1];
            float rv = rinv[d * 4 + hh];
            float4 acc = make_float4(0.f, 0.f, 0.f, 0.f);
            for (int p = beg; p < end; ++p) {
                float w = sex[p * 4 + hh];
                const float4 v = *(const float4*)(sxh + scsr[p] * HFEAT + lane * 4);
                acc.x = fmaf(w, v.x, acc.x);
                acc.y = fmaf(w, v.y, acc.y);
                acc.z = fmaf(w, v.z, acc.z);
                acc.w = fmaf(w, v.w, acc.w);
            }
            float4 r;
            r.x = fmaxf(fmaf(acc.x * rv, sc.x, bs.x), 0.0f);
            r.y = fmaxf(fmaf(acc.y * rv, sc.y, bs.y), 0.0f);
            r.z = fmaxf(fmaf(acc.z * rv, sc.z, bs.z), 0.0f);
            r.w = fmaxf(fmaf(acc.w * rv, sc.w, bs.w), 0.0f);
            *(float4*)(sh + d * HFEAT + lane * 4) = r;
        }
    }
    __syncthreads();   // sex reads done -> sW region reusable

    // stage W1 over sex/sW + layer-1 attention + BN1 fold
    for (int i = tid; i < HFEAT * HFEAT / 4; i += NTHREADS)
        *(float4*)(sW + i * 4) = *(const float4*)(g1w + i * 4);
    if (tid < 128) {
        float sc = bn1g[tid] * rsqrtf(bn1v[tid] + 1e-5f);
        sscale[tid] = sc;
        sbias[tid]  = fmaf(g1b[tid] - bn1m[tid], sc, bn1b[tid]);
        satt[tid]       = g1as[tid];
        satt[128 + tid] = g1ad[tid];
    }
    __syncthreads();

    // ==================== GAT layer 1 ====================
    gemm_sk(sh, sW, sxh, tid);
    __syncthreads();

    // scores: warp per node, full 32-lane reduce
    {
        float4 a1 = *(const float4*)(satt + lane * 4);
        float4 a2 = *(const float4*)(satt + 128 + lane * 4);
        for (int nd = wid; nd < NNODE; nd += 16) {
            float4 v = *(const float4*)(sxh + nd * HFEAT + lane * 4);
            float ss = v.x*a1.x + v.y*a1.y + v.z*a1.z + v.w*a1.w;
            float dd = v.x*a2.x + v.y*a2.y + v.z*a2.z + v.w*a2.w;
#pragma unroll
            for (int o = 16; o; o >>= 1) {
                ss += __shfl_xor_sync(0xffffffffu, ss, o);
                dd += __shfl_xor_sync(0xffffffffu, dd, o);
            }
            if (lane == 0) { s_s[nd] = ss; s_d[nd] = dd; }
        }
    }
    __syncthreads();   // ends sW(g1w) reads -> sex writable

    if (tid < 128) {
        int d = tid;
        int beg = sptr[d], end = sptr[d + 1];
        float sd = s_d[d];
        float mx = -1e30f;
        for (int p = beg; p < end; ++p) {
            float e = s_s[scsr[p]] + sd;
            e = (e > 0.0f) ? e : 0.2f * e;
            sex[p] = e;
            mx = fmaxf(mx, e);
        }
        float sum = 0.0f;
        for (int p = beg; p < end; ++p) {
            float ex = __expf(sex[p] - mx);
            sex[p] = ex;
            sum += ex;
        }
        rinv[d] = 1.0f / sum;
    }
    __syncthreads();

    // aggregate + BN1 + relu -> sh
    {
        float4 sc = *(const float4*)(sscale + lane * 4);
        float4 bs = *(const float4*)(sbias + lane * 4);
        for (int d = wid; d < NNODE; d += 16) {
            int beg = sptr[d], end = sptr[d + 1];
            float rv = rinv[d];
            float4 acc = make_float4(0.f, 0.f, 0.f, 0.f);
            for (int p = beg; p < end; ++p) {
                float w = sex[p];
                const float4 v = *(const float4*)(sxh + scsr[p] * HFEAT + lane * 4);
                acc.x = fmaf(w, v.x, acc.x);
                acc.y = fmaf(w, v.y, acc.y);
                acc.z = fmaf(w, v.z, acc.z);
                acc.w = fmaf(w, v.w, acc.w);
            }
            float4 r;
            r.x = fmaxf(fmaf(acc.x * rv, sc.x, bs.x), 0.0f);
            r.y = fmaxf(fmaf(acc.y * rv, sc.y, bs.y), 0.0f);
            r.z = fmaxf(fmaf(acc.z * rv, sc.z, bs.z), 0.0f);
            r.w = fmaxf(fmaf(acc.w * rv, sc.w, bs.w), 0.0f);
            *(float4*)(sh + d * HFEAT + lane * 4) = r;
        }
    }
    __syncthreads();

    // -------- mean pool --------
    {
        int g = tid >> 7, f = tid & 127;
        float acc = 0.0f;
#pragma unroll 4
        for (int n = g * 32; n < g * 32 + 32; ++n) acc += sh[n * HFEAT + f];
        pool[g * 128 + f] = acc;
    }
    __syncthreads();
    if (tid < 128)
        hp[tid] = (pool[tid] + pool[128 + tid] + pool[256 + tid] + pool[384 + tid])
                  * (1.0f / 128.0f);
    __syncthreads();

    // -------- MLP --------
    if (tid < 64) {
        float acc = b1[tid];
#pragma unroll 8
        for (int f = 0; f < 128; ++f) acc = fmaf(hp[f], w1[f * 64 + tid], acc);
        zz[tid] = fmaxf(acc, 0.0f);
    }
    __syncthreads();
    if (tid == 0) {
        float acc = b2[0];
#pragma unroll
        for (int j = 0; j < 64; ++j) acc = fmaf(zz[j], w2[j], acc);
        out[b] = acc;
    }
}

// ---------------------------------------------------------------------------
extern "C" void kernel_launch(void* const* d_in, const int* in_sizes, int n_in,
                              void* d_out, int out_size) {
    (void)in_sizes; (void)n_in; (void)out_size;
    const float* x    = (const float*)d_in[0];
    const int*   ei   = (const int*)d_in[1];
    const float* w_in = (const float*)d_in[2];
    const float* b_in = (const float*)d_in[3];
    const float* g0w  = (const float*)d_in[4];
    const float* g0as = (const float*)d_in[5];
    const float* g0ad = (const float*)d_in[6];
    const float* g0b  = (const float*)d_in[7];
    const float* bn0g = (const float*)d_in[8];
    const float* bn0b = (const float*)d_in[9];
    const float* bn0m = (const float*)d_in[10];
    const float* bn0v = (const float*)d_in[11];
    const float* g1w  = (const float*)d_in[12];
    const float* g1as = (const float*)d_in[13];
    const float* g1ad = (const float*)d_in[14];
    const float* g1b  = (const float*)d_in[15];
    const float* bn1g = (const float*)d_in[16];
    const float* bn1b = (const float*)d_in[17];
    const float* bn1m = (const float*)d_in[18];
    const float* bn1v = (const float*)d_in[19];
    const float* w1   = (const float*)d_in[20];
    const float* b1   = (const float*)d_in[21];
    const float* w2   = (const float*)d_in[22];
    const float* b2   = (const float*)d_in[23];
    float* out = (float*)d_out;

    cudaFuncSetAttribute(gnn_kernel,
                         cudaFuncAttributeMaxDynamicSharedMemorySize, SMEM_BYTES);

    build_csr_kernel<<<1, 1024>>>(ei);
    gnn_kernel<<<NGRAPH, NTHREADS, SMEM_BYTES>>>(
        x, w_in, b_in,
        g0w, g0as, g0ad, g0b, bn0g, bn0b, bn0m, bn0v,
        g1w, g1as, g1ad, g1b, bn1g, bn1b, bn1m, bn1v,
        w1, b1, w2, b2, out);
}

// round 8
// speedup vs baseline: 1.5405x; 1.2241x over previous
#include <cuda_runtime.h>

#define NNODE  128
#define NEDGE  1024
#define ETOT   1152
#define HFEAT  128
#define NGRAPH 1024
#define NTHREADS 512

// ---------------------------------------------------------------------------
// Device-global setup state (rebuilt every launch; deterministic).
// ---------------------------------------------------------------------------
__device__ int   g_csr_ptr[NNODE + 1];
__device__ int   g_csr_src[ETOT];
__device__ float g_t[HFEAT];                 // sorted relu breakpoints
__device__ float g_A[(HFEAT + 1) * HFEAT];   // interval slopes   (129 x 128)
__device__ float g_B[(HFEAT + 1) * HFEAT];   // interval offsets  (129 x 128)

__global__ void build_csr_kernel(const int* __restrict__ ei) {
    __shared__ int s_src[NEDGE];
    __shared__ int s_dst[NEDGE];
    __shared__ int cnt[NNODE];
    __shared__ int base[NNODE + 1];
    int t = threadIdx.x;
    if (t < NEDGE) { s_src[t] = ei[t]; s_dst[t] = ei[NEDGE + t]; }
    if (t < NNODE) cnt[t] = 0;
    __syncthreads();
    if (t < NEDGE) atomicAdd(&cnt[s_dst[t]], 1);
    __syncthreads();
    if (t == 0) {
        int acc = 0;
        for (int d = 0; d < NNODE; ++d) { base[d] = acc; acc += cnt[d] + 1; }
        base[NNODE] = acc;
    }
    __syncthreads();
    if (t <= NNODE) g_csr_ptr[t] = base[t];
    if (t < NEDGE) {
        int d = s_dst[t];
        int rank = 0;
        for (int e = 0; e < t; ++e) rank += (s_dst[e] == d) ? 1 : 0;
        g_csr_src[base[d] + rank] = s_src[t];
    }
    if (t < NNODE) g_csr_src[base[t] + cnt[t]] = t;  // self loop last
}

// ---------------------------------------------------------------------------
// Piecewise-linear composite of  xh0[n,c] = sum_f relu(x_n*w_f + b_f) * W[f,c].
// As a function of the scalar x_n this is continuous piecewise-linear with
// breakpoints t_f = -b_f/w_f.  Build sorted breakpoints + per-interval
// prefix tables A_j, B_j so that  xh0 = x*A_j + B_j,  j = #{t <= x}.
// One block of 128 threads; thread = output column.
// ---------------------------------------------------------------------------
__global__ void build_pwl_kernel(const float* __restrict__ w_in,
                                 const float* __restrict__ b_in,
                                 const float* __restrict__ W) {
    __shared__ float sw[HFEAT], sb[HFEAT], st[HFEAT];
    __shared__ int   ord[HFEAT];
    const int t = threadIdx.x;  // 0..127
    sw[t] = w_in[t];
    sb[t] = b_in[t];
    __syncthreads();
    const float wf = sw[t], bf = sb[t];
    const float INF = __int_as_float(0x7f800000);
    float tf = (wf == 0.0f) ? INF : (-bf / wf);
    st[t] = tf;
    __syncthreads();
    tf = st[t];
    int rank = 0;
    for (int g = 0; g < HFEAT; ++g) {
        float tg = st[g];
        rank += (tg < tf) || (tg == tf && g < t);
    }
    ord[rank] = t;
    __syncthreads();
    g_t[t] = st[ord[t]];

    // column scan: initial active set = {w<0} plus constant {w==0, b>0}
    const int c = t;
    float A = 0.0f, B = 0.0f;
    for (int f = 0; f < HFEAT; ++f) {
        float Wfc = W[f * HFEAT + c];
        float w = sw[f];
        if (w < 0.0f)                          { A += w * Wfc; B += sb[f] * Wfc; }
        else if (w == 0.0f && sb[f] > 0.0f)    { B += sb[f] * Wfc; }
    }
    g_A[c] = A; g_B[c] = B;
    for (int j = 0; j < HFEAT; ++j) {
        int f = ord[j];
        float w = sw[f];
        float Wfc = W[f * HFEAT + c];
        if (w > 0.0f)      { A += w * Wfc; B += sb[f] * Wfc; }
        else if (w < 0.0f) { A -= w * Wfc; B -= sb[f] * Wfc; }
        g_A[(j + 1) * HFEAT + c] = A;
        g_B[(j + 1) * HFEAT + c] = B;
    }
}

// ---------------------------------------------------------------------------
// Shared memory layout (pitch 128)
// ---------------------------------------------------------------------------
constexpr int OFF_SH    = 0;
constexpr int OFF_SXH   = OFF_SH  + NNODE * HFEAT;       // 16384
constexpr int OFF_SW    = OFF_SXH + NNODE * HFEAT;       // 16384 (sex overlaid)
constexpr int OFF_SS    = OFF_SW  + HFEAT * HFEAT;
constexpr int OFF_SD    = OFF_SS  + 512;
constexpr int OFF_RINV  = OFF_SD  + 512;
constexpr int OFF_SATT  = OFF_RINV + 512;
constexpr int OFF_SCALE = OFF_SATT + 256;
constexpr int OFF_BIAS  = OFF_SCALE + 128;
constexpr int OFF_POOL  = OFF_BIAS + 128;
constexpr int OFF_HP    = OFF_POOL + 512;
constexpr int OFF_ZZ    = OFF_HP + 128;
constexpr int OFF_T     = OFF_ZZ + 64;                   // 128: sorted breakpoints
constexpr int OFF_XV    = OFF_T + 128;                   // 128: x per node
constexpr int OFF_JX    = OFF_XV + 128;                  // 128: interval index
constexpr int SM_FLOATS = OFF_JX + 128;
constexpr int SM_INTS   = 132 + ETOT;
constexpr int SMEM_BYTES = SM_FLOATS * 4 + SM_INTS * 4;   // ~215 KB

// ---------------------------------------------------------------------------
// Packed fp32x2 helpers (f32x2 ops are PTX-only)
// ---------------------------------------------------------------------------
__device__ __forceinline__ unsigned long long pack2(float a) {
    unsigned long long r;
    unsigned int ai = __float_as_uint(a);
    asm("mov.b64 %0, {%1, %1};" : "=l"(r) : "r"(ai));
    return r;
}
__device__ __forceinline__ void ffma2(unsigned long long& d,
                                      unsigned long long a,
                                      unsigned long long b) {
    asm("fma.rn.f32x2 %0, %1, %2, %0;" : "+l"(d) : "l"(a), "l"(b));
}
__device__ __forceinline__ void fadd2(unsigned long long& d,
                                      unsigned long long a) {
    asm("add.rn.f32x2 %0, %0, %1;" : "+l"(d) : "l"(a));
}

// ---------------------------------------------------------------------------
// Split-K GEMM (unchanged from R7): C = A @ W, all SMEM, 16 warps, 8x8 tiles.
// One internal __syncthreads(); all 512 threads must call.
// ---------------------------------------------------------------------------
__device__ __forceinline__ void gemm_sk(const float* __restrict__ A,
                                        const float* __restrict__ sW,
                                        float* __restrict__ C, int tid) {
    const int w  = tid >> 5;
    const int l  = tid & 31;
    const int kh = w >> 3;
    const int r0 = (w & 7) * 16 + (l >> 4) * 8;
    const int ca = (l & 15) * 4;
    const int k0 = kh * 64;

    unsigned long long acc[8][4];
#pragma unroll
    for (int i = 0; i < 8; ++i)
#pragma unroll
        for (int j = 0; j < 4; ++j) acc[i][j] = 0ull;

#pragma unroll 2
    for (int k = k0; k < k0 + 64; k += 2) {
        float2 a[8];
#pragma unroll
        for (int i = 0; i < 8; ++i)
            a[i] = *(const float2*)(A + (r0 + i) * HFEAT + k);
        ulonglong2 w00 = *(const ulonglong2*)(sW + k * HFEAT + ca);
        ulonglong2 w01 = *(const ulonglong2*)(sW + k * HFEAT + ca + 64);
        ulonglong2 w10 = *(const ulonglong2*)(sW + (k + 1) * HFEAT + ca);
        ulonglong2 w11 = *(const ulonglong2*)(sW + (k + 1) * HFEAT + ca + 64);
#pragma unroll
        for (int i = 0; i < 8; ++i) {
            unsigned long long ax = pack2(a[i].x);
            unsigned long long ay = pack2(a[i].y);
            ffma2(acc[i][0], ax, w00.x);
            ffma2(acc[i][1], ax, w00.y);
            ffma2(acc[i][2], ax, w01.x);
            ffma2(acc[i][3], ax, w01.y);
            ffma2(acc[i][0], ay, w10.x);
            ffma2(acc[i][1], ay, w10.y);
            ffma2(acc[i][2], ay, w11.x);
            ffma2(acc[i][3], ay, w11.y);
        }
    }

    if (kh == 1) {
#pragma unroll
        for (int i = 0; i < 8; ++i) {
            ulonglong2 s0, s1;
            s0.x = acc[i][0]; s0.y = acc[i][1];
            s1.x = acc[i][2]; s1.y = acc[i][3];
            *(ulonglong2*)(C + (r0 + i) * HFEAT + ca)      = s0;
            *(ulonglong2*)(C + (r0 + i) * HFEAT + ca + 64) = s1;
        }
    }
    __syncthreads();
    if (kh == 0) {
#pragma unroll
        for (int i = 0; i < 8; ++i) {
            ulonglong2 p0 = *(const ulonglong2*)(C + (r0 + i) * HFEAT + ca);
            ulonglong2 p1 = *(const ulonglong2*)(C + (r0 + i) * HFEAT + ca + 64);
            fadd2(acc[i][0], p0.x);
            fadd2(acc[i][1], p0.y);
            fadd2(acc[i][2], p1.x);
            fadd2(acc[i][3], p1.y);
            ulonglong2 s0, s1;
            s0.x = acc[i][0]; s0.y = acc[i][1];
            s1.x = acc[i][2]; s1.y = acc[i][3];
            *(ulonglong2*)(C + (r0 + i) * HFEAT + ca)      = s0;
            *(ulonglong2*)(C + (r0 + i) * HFEAT + ca + 64) = s1;
        }
    }
}

__global__ __launch_bounds__(NTHREADS, 1)
void gnn_kernel(const float* __restrict__ x,
                const float* __restrict__ g0as, const float* __restrict__ g0ad,
                const float* __restrict__ g0b,
                const float* __restrict__ bn0g, const float* __restrict__ bn0b,
                const float* __restrict__ bn0m, const float* __restrict__ bn0v,
                const float* __restrict__ g1w, const float* __restrict__ g1as,
                const float* __restrict__ g1ad, const float* __restrict__ g1b,
                const float* __restrict__ bn1g, const float* __restrict__ bn1b,
                const float* __restrict__ bn1m, const float* __restrict__ bn1v,
                const float* __restrict__ w1, const float* __restrict__ b1,
                const float* __restrict__ w2, const float* __restrict__ b2,
                float* __restrict__ out) {
    extern __shared__ float smem[];
    float* sh    = smem + OFF_SH;
    float* sxh   = smem + OFF_SXH;
    float* sW    = smem + OFF_SW;
    float* sex   = smem + OFF_SW;     // overlaid: sex (L0) done before W1 staged
    float* s_s   = smem + OFF_SS;
    float* s_d   = smem + OFF_SD;
    float* rinv  = smem + OFF_RINV;
    float* satt  = smem + OFF_SATT;
    float* sscale= smem + OFF_SCALE;
    float* sbias = smem + OFF_BIAS;
    float* pool  = smem + OFF_POOL;
    float* hp    = smem + OFF_HP;
    float* zz    = smem + OFF_ZZ;
    float* st    = smem + OFF_T;
    float* sxv   = smem + OFF_XV;
    int*   jidx  = (int*)(smem + OFF_JX);
    int*   sptr  = (int*)(smem + SM_FLOATS);
    int*   scsr  = sptr + 132;

    const int tid  = threadIdx.x;
    const int wid  = tid >> 5;
    const int lane = tid & 31;
    const int b    = blockIdx.x;

    // stage CSR + breakpoints
    for (int i = tid; i <= NNODE; i += NTHREADS) sptr[i] = g_csr_ptr[i];
    for (int i = tid; i < ETOT; i += NTHREADS)   scsr[i] = g_csr_src[i];
    if (tid < 128) st[tid] = g_t[tid];

    // layer-0 attention + BN0 fold
    if (tid < 128) {
        satt[tid]       = g0as[tid];
        satt[128 + tid] = g0ad[tid];
        float sc = bn0g[tid] * rsqrtf(bn0v[tid] + 1e-5f);
        sscale[tid] = sc;
        sbias[tid]  = fmaf(g0b[tid] - bn0m[tid], sc, bn0b[tid]);
    }
    __syncthreads();

    // per-node interval index: j = #{t <= x}
    if (tid < 128) {
        float xv = x[b * NNODE + tid];
        sxv[tid] = xv;
        int lo = 0, hi = HFEAT;
        while (lo < hi) {
            int mid = (lo + hi) >> 1;
            if (st[mid] <= xv) lo = mid + 1; else hi = mid;
        }
        jidx[tid] = lo;
    }
    __syncthreads();

    // ========== xh0 = x*A_j + B_j  (replaces proj + GEMM0), fused scores =====
    {
        float4 a1 = *(const float4*)(satt + lane * 4);        // a_s (head=lane>>3)
        float4 a2 = *(const float4*)(satt + 128 + lane * 4);  // a_d
        for (int n = wid; n < NNODE; n += 16) {
            int   j  = jidx[n];
            float xv = sxv[n];
            float4 A0 = *(const float4*)(g_A + j * HFEAT + lane * 4);
            float4 B0 = *(const float4*)(g_B + j * HFEAT + lane * 4);
            float4 v;
            v.x = fmaf(xv, A0.x, B0.x);
            v.y = fmaf(xv, A0.y, B0.y);
            v.z = fmaf(xv, A0.z, B0.z);
            v.w = fmaf(xv, A0.w, B0.w);
            *(float4*)(sxh + n * HFEAT + lane * 4) = v;
            float ss = v.x*a1.x + v.y*a1.y + v.z*a1.z + v.w*a1.w;
            float dd = v.x*a2.x + v.y*a2.y + v.z*a2.z + v.w*a2.w;
#pragma unroll
            for (int o = 4; o; o >>= 1) {
                ss += __shfl_xor_sync(0xffffffffu, ss, o);
                dd += __shfl_xor_sync(0xffffffffu, dd, o);
            }
            if ((lane & 7) == 0) {
                s_s[n * 4 + (lane >> 3)] = ss;
                s_d[n * 4 + (lane >> 3)] = dd;
            }
        }
    }
    __syncthreads();

    // softmax per (dst, head): pass1 caches leaky(e), pass2 exps
    {
        int d  = tid & 127;
        int hh = tid >> 7;
        int beg = sptr[d], end = sptr[d + 1];
        float sd = s_d[d * 4 + hh];
        float mx = -1e30f;
        for (int p = beg; p < end; ++p) {
            float e = s_s[scsr[p] * 4 + hh] + sd;
            e = (e > 0.0f) ? e : 0.2f * e;
            sex[p * 4 + hh] = e;
            mx = fmaxf(mx, e);
        }
        float sum = 0.0f;
        for (int p = beg; p < end; ++p) {
            float ex = __expf(sex[p * 4 + hh] - mx);
            sex[p * 4 + hh] = ex;
            sum += ex;
        }
        rinv[d * 4 + hh] = 1.0f / sum;
    }
    __syncthreads();

    // aggregate + BN0 + relu (warp-per-node, float4 per lane) -> sh
    {
        int hh = lane >> 3;
        float4 sc = *(const float4*)(sscale + lane * 4);
        float4 bs = *(const float4*)(sbias + lane * 4);
        for (int d = wid; d < NNODE; d += 16) {
            int beg = sptr[d], end = sptr[d + 1];
            float rv = rinv[d * 4 + hh];
            float4 acc = make_float4(0.f, 0.f, 0.f, 0.f);
            for (int p = beg; p < end; ++p) {
                float w = sex[p * 4 + hh];
                const float4 v = *(const float4*)(sxh + scsr[p] * HFEAT + lane * 4);
                acc.x = fmaf(w, v.x, acc.x);
                acc.y = fmaf(w, v.y, acc.y);
                acc.z = fmaf(w, v.z, acc.z);
                acc.w = fmaf(w, v.w, acc.w);
            }
            float4 r;
            r.x = fmaxf(fmaf(acc.x * rv, sc.x, bs.x), 0.0f);
            r.y = fmaxf(fmaf(acc.y * rv, sc.y, bs.y), 0.0f);
            r.z = fmaxf(fmaf(acc.z * rv, sc.z, bs.z), 0.0f);
            r.w = fmaxf(fmaf(acc.w * rv, sc.w, bs.w), 0.0f);
            *(float4*)(sh + d * HFEAT + lane * 4) = r;
        }
    }
    __syncthreads();   // sex reads done -> sW region reusable

    // stage W1 over sex/sW + layer-1 attention + BN1 fold
    for (int i = tid; i < HFEAT * HFEAT / 4; i += NTHREADS)
        *(float4*)(sW + i * 4) = *(const float4*)(g1w + i * 4);
    if (tid < 128) {
        float sc = bn1g[tid] * rsqrtf(bn1v[tid] + 1e-5f);
        sscale[tid] = sc;
        sbias[tid]  = fmaf(g1b[tid] - bn1m[tid], sc, bn1b[tid]);
        satt[tid]       = g1as[tid];
        satt[128 + tid] = g1ad[tid];
    }
    __syncthreads();

    // ==================== GAT layer 1 ====================
    gemm_sk(sh, sW, sxh, tid);
    __syncthreads();

    // scores: warp per node, full 32-lane reduce
    {
        float4 a1 = *(const float4*)(satt + lane * 4);
        float4 a2 = *(const float4*)(satt + 128 + lane * 4);
        for (int nd = wid; nd < NNODE; nd += 16) {
            float4 v = *(const float4*)(sxh + nd * HFEAT + lane * 4);
            float ss = v.x*a1.x + v.y*a1.y + v.z*a1.z + v.w*a1.w;
            float dd = v.x*a2.x + v.y*a2.y + v.z*a2.z + v.w*a2.w;
#pragma unroll
            for (int o = 16; o; o >>= 1) {
                ss += __shfl_xor_sync(0xffffffffu, ss, o);
                dd += __shfl_xor_sync(0xffffffffu, dd, o);
            }
            if (lane == 0) { s_s[nd] = ss; s_d[nd] = dd; }
        }
    }
    __syncthreads();   // ends sW(g1w) reads -> sex writable

    if (tid < 128) {
        int d = tid;
        int beg = sptr[d], end = sptr[d + 1];
        float sd = s_d[d];
        float mx = -1e30f;
        for (int p = beg; p < end; ++p) {
            float e = s_s[scsr[p]] + sd;
            e = (e > 0.0f) ? e : 0.2f * e;
            sex[p] = e;
            mx = fmaxf(mx, e);
        }
        float sum = 0.0f;
        for (int p = beg; p < end; ++p) {
            float ex = __expf(sex[p] - mx);
            sex[p] = ex;
            sum += ex;
        }
        rinv[d] = 1.0f / sum;
    }
    __syncthreads();

    // aggregate + BN1 + relu -> sh
    {
        float4 sc = *(const float4*)(sscale + lane * 4);
        float4 bs = *(const float4*)(sbias + lane * 4);
        for (int d = wid; d < NNODE; d += 16) {
            int beg = sptr[d], end = sptr[d + 1];
            float rv = rinv[d];
            float4 acc = make_float4(0.f, 0.f, 0.f, 0.f);
            for (int p = beg; p < end; ++p) {
                float w = sex[p];
                const float4 v = *(const float4*)(sxh + scsr[p] * HFEAT + lane * 4);
                acc.x = fmaf(w, v.x, acc.x);
                acc.y = fmaf(w, v.y, acc.y);
                acc.z = fmaf(w, v.z, acc.z);
                acc.w = fmaf(w, v.w, acc.w);
            }
            float4 r;
            r.x = fmaxf(fmaf(acc.x * rv, sc.x, bs.x), 0.0f);
            r.y = fmaxf(fmaf(acc.y * rv, sc.y, bs.y), 0.0f);
            r.z = fmaxf(fmaf(acc.z * rv, sc.z, bs.z), 0.0f);
            r.w = fmaxf(fmaf(acc.w * rv, sc.w, bs.w), 0.0f);
            *(float4*)(sh + d * HFEAT + lane * 4) = r;
        }
    }
    __syncthreads();

    // -------- mean pool --------
    {
        int g = tid >> 7, f = tid & 127;
        float acc = 0.0f;
#pragma unroll 4
        for (int n = g * 32; n < g * 32 + 32; ++n) acc += sh[n * HFEAT + f];
        pool[g * 128 + f] = acc;
    }
    __syncthreads();
    if (tid < 128)
        hp[tid] = (pool[tid] + pool[128 + tid] + pool[256 + tid] + pool[384 + tid])
                  * (1.0f / 128.0f);
    __syncthreads();

    // -------- MLP --------
    if (tid < 64) {
        float acc = b1[tid];
#pragma unroll 8
        for (int f = 0; f < 128; ++f) acc = fmaf(hp[f], w1[f * 64 + tid], acc);
        zz[tid] = fmaxf(acc, 0.0f);
    }
    __syncthreads();
    if (tid == 0) {
        float acc = b2[0];
#pragma unroll
        for (int j = 0; j < 64; ++j) acc = fmaf(zz[j], w2[j], acc);
        out[b] = acc;
    }
}

// ---------------------------------------------------------------------------
extern "C" void kernel_launch(void* const* d_in, const int* in_sizes, int n_in,
                              void* d_out, int out_size) {
    (void)in_sizes; (void)n_in; (void)out_size;
    const float* x    = (const float*)d_in[0];
    const int*   ei   = (const int*)d_in[1];
    const float* w_in = (const float*)d_in[2];
    const float* b_in = (const float*)d_in[3];
    const float* g0w  = (const float*)d_in[4];
    const float* g0as = (const float*)d_in[5];
    const float* g0ad = (const float*)d_in[6];
    const float* g0b  = (const float*)d_in[7];
    const float* bn0g = (const float*)d_in[8];
    const float* bn0b = (const float*)d_in[9];
    const float* bn0m = (const float*)d_in[10];
    const float* bn0v = (const float*)d_in[11];
    const float* g1w  = (const float*)d_in[12];
    const float* g1as = (const float*)d_in[13];
    const float* g1ad = (const float*)d_in[14];
    const float* g1b  = (const float*)d_in[15];
    const float* bn1g = (const float*)d_in[16];
    const float* bn1b = (const float*)d_in[17];
    const float* bn1m = (const float*)d_in[18];
    const float* bn1v = (const float*)d_in[19];
    const float* w1   = (const float*)d_in[20];
    const float* b1   = (const float*)d_in[21];
    const float* w2   = (const float*)d_in[22];
    const float* b2   = (const float*)d_in[23];
    float* out = (float*)d_out;

    cudaFuncSetAttribute(gnn_kernel,
                         cudaFuncAttributeMaxDynamicSharedMemorySize, SMEM_BYTES);

    build_csr_kernel<<<1, 1024>>>(ei);
    build_pwl_kernel<<<1, 128>>>(w_in, b_in, g0w);
    gnn_kernel<<<NGRAPH, NTHREADS, SMEM_BYTES>>>(
        x, g0as, g0ad, g0b, bn0g, bn0b, bn0m, bn0v,
        g1w, g1as, g1ad, g1b, bn1g, bn1b, bn1m, bn1v,
        w1, b1, w2, b2, out);
}

// round 9
// speedup vs baseline: 1.6225x; 1.0532x over previous
#include <cuda_runtime.h>

#define NNODE  128
#define NEDGE  1024
#define ETOT   1152
#define HFEAT  128
#define NGRAPH 1024
#define NTHREADS 512

// ---------------------------------------------------------------------------
// Device-global setup state (rebuilt every launch; deterministic).
// ---------------------------------------------------------------------------
__device__ int   g_csr_ptr[NNODE + 1];
__device__ int   g_csr_src[ETOT];
__device__ float g_t[HFEAT];                 // sorted relu breakpoints
__device__ float g_A[(HFEAT + 1) * HFEAT];   // interval slopes   (129 x 128)
__device__ float g_B[(HFEAT + 1) * HFEAT];   // interval offsets  (129 x 128)

// ---------------------------------------------------------------------------
// Combined setup: block 0 = CSR (1024 thr, warp-match stable ranks),
//                 block 1 = PWL tables (128 thr active).
// ---------------------------------------------------------------------------
__global__ void setup_kernel(const int* __restrict__ ei,
                             const float* __restrict__ w_in,
                             const float* __restrict__ b_in,
                             const float* __restrict__ W) {
    if (blockIdx.x == 0) {
        __shared__ int s_src[NEDGE];
        __shared__ int s_dst[NEDGE];
        __shared__ int hist[32][NNODE];      // per-chunk dst histogram -> prefix
        __shared__ int cnt[NNODE];
        __shared__ int base[NNODE + 1];
        const int t = threadIdx.x;
        const int w = t >> 5, l = t & 31;
        s_src[t] = ei[t];
        s_dst[t] = ei[NEDGE + t];
        for (int i = t; i < 32 * NNODE; i += 1024) ((int*)hist)[i] = 0;
        __syncthreads();
        const int d = s_dst[t];
        unsigned mask = __match_any_sync(0xffffffffu, d);
        int lane_rank = __popc(mask & ((1u << l) - 1u));
        if (l == (__ffs(mask) - 1)) hist[w][d] = __popc(mask);
        __syncthreads();
        if (t < NNODE) {            // exclusive prefix over chunks, per dst
            int acc = 0;
#pragma unroll
            for (int c = 0; c < 32; ++c) {
                int v = hist[c][t];
                hist[c][t] = acc;
                acc += v;
            }
            cnt[t] = acc;
        }
        __syncthreads();
        if (t == 0) {
            int acc = 0;
            for (int dd = 0; dd < NNODE; ++dd) { base[dd] = acc; acc += cnt[dd] + 1; }
            base[NNODE] = acc;
        }
        __syncthreads();
        if (t <= NNODE) g_csr_ptr[t] = base[t];
        g_csr_src[base[d] + hist[w][d] + lane_rank] = s_src[t];
        if (t < NNODE) g_csr_src[base[t] + cnt[t]] = t;   // self loop last
    } else {
        __shared__ float sw[HFEAT], sb[HFEAT], st[HFEAT];
        __shared__ int   ord[HFEAT];
        const int t = threadIdx.x;
        if (t >= HFEAT) return;
        sw[t] = w_in[t];
        sb[t] = b_in[t];
        __syncthreads();
        const float wf = sw[t], bf = sb[t];
        const float INF = __int_as_float(0x7f800000);
        float tf = (wf == 0.0f) ? INF : (-bf / wf);
        st[t] = tf;
        __syncthreads();
        tf = st[t];
        int rank = 0;
        for (int g = 0; g < HFEAT; ++g) {
            float tg = st[g];
            rank += (tg < tf) || (tg == tf && g < t);
        }
        ord[rank] = t;
        __syncthreads();
        g_t[t] = st[ord[t]];

        const int c = t;
        float A = 0.0f, B = 0.0f;
        for (int f = 0; f < HFEAT; ++f) {
            float Wfc = W[f * HFEAT + c];
            float w = sw[f];
            if (w < 0.0f)                       { A += w * Wfc; B += sb[f] * Wfc; }
            else if (w == 0.0f && sb[f] > 0.0f) { B += sb[f] * Wfc; }
        }
        g_A[c] = A; g_B[c] = B;
        for (int j = 0; j < HFEAT; ++j) {
            int f = ord[j];
            float w = sw[f];
            float Wfc = W[f * HFEAT + c];
            if (w > 0.0f)      { A += w * Wfc; B += sb[f] * Wfc; }
            else if (w < 0.0f) { A -= w * Wfc; B -= sb[f] * Wfc; }
            g_A[(j + 1) * HFEAT + c] = A;
            g_B[(j + 1) * HFEAT + c] = B;
        }
    }
}

// ---------------------------------------------------------------------------
// Shared memory layout (pitch 128). sW holds g1w for the WHOLE kernel.
// ---------------------------------------------------------------------------
constexpr int OFF_SH    = 0;
constexpr int OFF_SXH   = OFF_SH  + NNODE * HFEAT;       // 16384
constexpr int OFF_SW    = OFF_SXH + NNODE * HFEAT;       // 16384 (g1w resident)
constexpr int OFF_SEX   = OFF_SW  + HFEAT * HFEAT;       // 4608
constexpr int OFF_SS    = OFF_SEX + ETOT * 4;            // 512 (pool aliases)
constexpr int OFF_SD    = OFF_SS  + 512;
constexpr int OFF_RINV  = OFF_SD  + 512;
constexpr int OFF_SATT  = OFF_RINV + 512;                // 256
constexpr int OFF_SCALE = OFF_SATT + 256;                // 128
constexpr int OFF_BIAS  = OFF_SCALE + 128;               // 128
constexpr int OFF_HP    = OFF_BIAS + 128;                // 128
constexpr int OFF_ZZ    = OFF_HP + 128;                  // 64
constexpr int OFF_XV    = OFF_ZZ + 64;                   // 128
constexpr int OFF_JX    = OFF_XV + 128;                  // 128
constexpr int SM_FLOATS = OFF_JX + 128;
constexpr int SM_INTS   = 132 + ETOT;
constexpr int SMEM_BYTES = SM_FLOATS * 4 + SM_INTS * 4;   // ~230.7 KB

// ---------------------------------------------------------------------------
// Packed fp32x2 helpers (f32x2 ops are PTX-only)
// ---------------------------------------------------------------------------
__device__ __forceinline__ unsigned long long pack2(float a) {
    unsigned long long r;
    unsigned int ai = __float_as_uint(a);
    asm("mov.b64 %0, {%1, %1};" : "=l"(r) : "r"(ai));
    return r;
}
__device__ __forceinline__ void ffma2(unsigned long long& d,
                                      unsigned long long a,
                                      unsigned long long b) {
    asm("fma.rn.f32x2 %0, %1, %2, %0;" : "+l"(d) : "l"(a), "l"(b));
}
__device__ __forceinline__ void fadd2(unsigned long long& d,
                                      unsigned long long a) {
    asm("add.rn.f32x2 %0, %0, %1;" : "+l"(d) : "l"(a));
}

// ---------------------------------------------------------------------------
// Split-K GEMM: C = A @ W, all SMEM, 16 warps, 8x8 thread tiles.
// One internal __syncthreads(); all 512 threads must call.
// ---------------------------------------------------------------------------
__device__ __forceinline__ void gemm_sk(const float* __restrict__ A,
                                        const float* __restrict__ sW,
                                        float* __restrict__ C, int tid) {
    const int w  = tid >> 5;
    const int l  = tid & 31;
    const int kh = w >> 3;
    const int r0 = (w & 7) * 16 + (l >> 4) * 8;
    const int ca = (l & 15) * 4;
    const int k0 = kh * 64;

    unsigned long long acc[8][4];
#pragma unroll
    for (int i = 0; i < 8; ++i)
#pragma unroll
        for (int j = 0; j < 4; ++j) acc[i][j] = 0ull;

#pragma unroll 2
    for (int k = k0; k < k0 + 64; k += 2) {
        float2 a[8];
#pragma unroll
        for (int i = 0; i < 8; ++i)
            a[i] = *(const float2*)(A + (r0 + i) * HFEAT + k);
        ulonglong2 w00 = *(const ulonglong2*)(sW + k * HFEAT + ca);
        ulonglong2 w01 = *(const ulonglong2*)(sW + k * HFEAT + ca + 64);
        ulonglong2 w10 = *(const ulonglong2*)(sW + (k + 1) * HFEAT + ca);
        ulonglong2 w11 = *(const ulonglong2*)(sW + (k + 1) * HFEAT + ca + 64);
#pragma unroll
        for (int i = 0; i < 8; ++i) {
            unsigned long long ax = pack2(a[i].x);
            unsigned long long ay = pack2(a[i].y);
            ffma2(acc[i][0], ax, w00.x);
            ffma2(acc[i][1], ax, w00.y);
            ffma2(acc[i][2], ax, w01.x);
            ffma2(acc[i][3], ax, w01.y);
            ffma2(acc[i][0], ay, w10.x);
            ffma2(acc[i][1], ay, w10.y);
            ffma2(acc[i][2], ay, w11.x);
            ffma2(acc[i][3], ay, w11.y);
        }
    }

    if (kh == 1) {
#pragma unroll
        for (int i = 0; i < 8; ++i) {
            ulonglong2 s0, s1;
            s0.x = acc[i][0]; s0.y = acc[i][1];
            s1.x = acc[i][2]; s1.y = acc[i][3];
            *(ulonglong2*)(C + (r0 + i) * HFEAT + ca)      = s0;
            *(ulonglong2*)(C + (r0 + i) * HFEAT + ca + 64) = s1;
        }
    }
    __syncthreads();
    if (kh == 0) {
#pragma unroll
        for (int i = 0; i < 8; ++i) {
            ulonglong2 p0 = *(const ulonglong2*)(C + (r0 + i) * HFEAT + ca);
            ulonglong2 p1 = *(const ulonglong2*)(C + (r0 + i) * HFEAT + ca + 64);
            fadd2(acc[i][0], p0.x);
            fadd2(acc[i][1], p0.y);
            fadd2(acc[i][2], p1.x);
            fadd2(acc[i][3], p1.y);
            ulonglong2 s0, s1;
            s0.x = acc[i][0]; s0.y = acc[i][1];
            s1.x = acc[i][2]; s1.y = acc[i][3];
            *(ulonglong2*)(C + (r0 + i) * HFEAT + ca)      = s0;
            *(ulonglong2*)(C + (r0 + i) * HFEAT + ca + 64) = s1;
        }
    }
}

__global__ __launch_bounds__(NTHREADS, 1)
void gnn_kernel(const float* __restrict__ x,
                const float* __restrict__ g0as, const float* __restrict__ g0ad,
                const float* __restrict__ g0b,
                const float* __restrict__ bn0g, const float* __restrict__ bn0b,
                const float* __restrict__ bn0m, const float* __restrict__ bn0v,
                const float* __restrict__ g1w, const float* __restrict__ g1as,
                const float* __restrict__ g1ad, const float* __restrict__ g1b,
                const float* __restrict__ bn1g, const float* __restrict__ bn1b,
                const float* __restrict__ bn1m, const float* __restrict__ bn1v,
                const float* __restrict__ w1, const float* __restrict__ b1,
                const float* __restrict__ w2, const float* __restrict__ b2,
                float* __restrict__ out) {
    extern __shared__ float smem[];
    float* sh    = smem + OFF_SH;
    float* sxh   = smem + OFF_SXH;
    float* sW    = smem + OFF_SW;
    float* sex   = smem + OFF_SEX;
    float* s_s   = smem + OFF_SS;
    float* s_d   = smem + OFF_SD;
    float* rinv  = smem + OFF_RINV;
    float* satt  = smem + OFF_SATT;
    float* sscale= smem + OFF_SCALE;
    float* sbias = smem + OFF_BIAS;
    float* pool  = smem + OFF_SS;     // aliases s_s+s_d (dead at pooling time)
    float* hp    = smem + OFF_HP;
    float* zz    = smem + OFF_ZZ;
    float* sxv   = smem + OFF_XV;
    int*   jidx  = (int*)(smem + OFF_JX);
    int*   sptr  = (int*)(smem + SM_FLOATS);
    int*   scsr  = sptr + 132;

    const int tid  = threadIdx.x;
    const int wid  = tid >> 5;
    const int lane = tid & 31;
    const int b    = blockIdx.x;

    // ---- init: CSR, W1 (resident all kernel), L0 att + BN0 fold, jidx ----
    for (int i = tid; i <= NNODE; i += NTHREADS) sptr[i] = g_csr_ptr[i];
    for (int i = tid; i < ETOT; i += NTHREADS)   scsr[i] = g_csr_src[i];
    for (int i = tid; i < HFEAT * HFEAT / 4; i += NTHREADS)
        *(float4*)(sW + i * 4) = *(const float4*)(g1w + i * 4);
    if (tid < 128) {
        satt[tid]       = g0as[tid];
        satt[128 + tid] = g0ad[tid];
        float sc = bn0g[tid] * rsqrtf(bn0v[tid] + 1e-5f);
        sscale[tid] = sc;
        sbias[tid]  = fmaf(g0b[tid] - bn0m[tid], sc, bn0b[tid]);
        // interval index: binary search global breakpoint table (L1-cached)
        float xv = x[b * NNODE + tid];
        sxv[tid] = xv;
        int lo = 0, hi = HFEAT;
        while (lo < hi) {
            int mid = (lo + hi) >> 1;
            if (g_t[mid] <= xv) lo = mid + 1; else hi = mid;
        }
        jidx[tid] = lo;
    }
    __syncthreads();

    // ---- xh0 = x*A_j + B_j (replaces proj + GEMM0) with fused L0 scores ----
    {
        float4 a1 = *(const float4*)(satt + lane * 4);        // a_s (head=lane>>3)
        float4 a2 = *(const float4*)(satt + 128 + lane * 4);  // a_d
        for (int n = wid; n < NNODE; n += 16) {
            int   j  = jidx[n];
            float xv = sxv[n];
            float4 A0 = *(const float4*)(g_A + j * HFEAT + lane * 4);
            float4 B0 = *(const float4*)(g_B + j * HFEAT + lane * 4);
            float4 v;
            v.x = fmaf(xv, A0.x, B0.x);
            v.y = fmaf(xv, A0.y, B0.y);
            v.z = fmaf(xv, A0.z, B0.z);
            v.w = fmaf(xv, A0.w, B0.w);
            *(float4*)(sxh + n * HFEAT + lane * 4) = v;
            float ss = v.x*a1.x + v.y*a1.y + v.z*a1.z + v.w*a1.w;
            float dd = v.x*a2.x + v.y*a2.y + v.z*a2.z + v.w*a2.w;
#pragma unroll
            for (int o = 4; o; o >>= 1) {
                ss += __shfl_xor_sync(0xffffffffu, ss, o);
                dd += __shfl_xor_sync(0xffffffffu, dd, o);
            }
            if ((lane & 7) == 0) {
                s_s[n * 4 + (lane >> 3)] = ss;
                s_d[n * 4 + (lane >> 3)] = dd;
            }
        }
    }
    __syncthreads();

    // ---- L0 softmax per (dst, head) ----
    {
        int d  = tid & 127;
        int hh = tid >> 7;
        int beg = sptr[d], end = sptr[d + 1];
        float sd = s_d[d * 4 + hh];
        float mx = -1e30f;
        for (int p = beg; p < end; ++p) {
            float e = s_s[scsr[p] * 4 + hh] + sd;
            e = (e > 0.0f) ? e : 0.2f * e;
            sex[p * 4 + hh] = e;
            mx = fmaxf(mx, e);
        }
        float sum = 0.0f;
        for (int p = beg; p < end; ++p) {
            float ex = __expf(sex[p * 4 + hh] - mx);
            sex[p * 4 + hh] = ex;
            sum += ex;
        }
        rinv[d * 4 + hh] = 1.0f / sum;
    }
    __syncthreads();

    // ---- L0 aggregate + BN0 + relu -> sh ----
    {
        int hh = lane >> 3;
        float4 sc = *(const float4*)(sscale + lane * 4);
        float4 bs = *(const float4*)(sbias + lane * 4);
        for (int d = wid; d < NNODE; d += 16) {
            int beg = sptr[d], end = sptr[d + 1];
            float rv = rinv[d * 4 + hh];
            float4 acc = make_float4(0.f, 0.f, 0.f, 0.f);
            for (int p = beg; p < end; ++p) {
                float w = sex[p * 4 + hh];
                const float4 v = *(const float4*)(sxh + scsr[p] * HFEAT + lane * 4);
                acc.x = fmaf(w, v.x, acc.x);
                acc.y = fmaf(w, v.y, acc.y);
                acc.z = fmaf(w, v.z, acc.z);
                acc.w = fmaf(w, v.w, acc.w);
            }
            float4 r;
            r.x = fmaxf(fmaf(acc.x * rv, sc.x, bs.x), 0.0f);
            r.y = fmaxf(fmaf(acc.y * rv, sc.y, bs.y), 0.0f);
            r.z = fmaxf(fmaf(acc.z * rv, sc.z, bs.z), 0.0f);
            r.w = fmaxf(fmaf(acc.w * rv, sc.w, bs.w), 0.0f);
            *(float4*)(sh + d * HFEAT + lane * 4) = r;
        }
    }
    __syncthreads();

    // restage L1 attention + BN1 fold (disjoint from gemm operands)
    if (tid < 128) {
        float sc = bn1g[tid] * rsqrtf(bn1v[tid] + 1e-5f);
        sscale[tid] = sc;
        sbias[tid]  = fmaf(g1b[tid] - bn1m[tid], sc, bn1b[tid]);
        satt[tid]       = g1as[tid];
        satt[128 + tid] = g1ad[tid];
    }

    // ==================== GAT layer 1 GEMM ====================
    gemm_sk(sh, sW, sxh, tid);
    __syncthreads();

    // ---- L1 scores: warp per node, full 32-lane reduce ----
    {
        float4 a1 = *(const float4*)(satt + lane * 4);
        float4 a2 = *(const float4*)(satt + 128 + lane * 4);
        for (int nd = wid; nd < NNODE; nd += 16) {
            float4 v = *(const float4*)(sxh + nd * HFEAT + lane * 4);
            float ss = v.x*a1.x + v.y*a1.y + v.z*a1.z + v.w*a1.w;
            float dd = v.x*a2.x + v.y*a2.y + v.z*a2.z + v.w*a2.w;
#pragma unroll
            for (int o = 16; o; o >>= 1) {
                ss += __shfl_xor_sync(0xffffffffu, ss, o);
                dd += __shfl_xor_sync(0xffffffffu, dd, o);
            }
            if (lane == 0) { s_s[nd] = ss; s_d[nd] = dd; }
        }
    }
    __syncthreads();

    // ---- L1 softmax ----
    if (tid < 128) {
        int d = tid;
        int beg = sptr[d], end = sptr[d + 1];
        float sd = s_d[d];
        float mx = -1e30f;
        for (int p = beg; p < end; ++p) {
            float e = s_s[scsr[p]] + sd;
            e = (e > 0.0f) ? e : 0.2f * e;
            sex[p] = e;
            mx = fmaxf(mx, e);
        }
        float sum = 0.0f;
        for (int p = beg; p < end; ++p) {
            float ex = __expf(sex[p] - mx);
            sex[p] = ex;
            sum += ex;
        }
        rinv[d] = 1.0f / sum;
    }
    __syncthreads();

    // ---- L1 aggregate + BN1 + relu -> sh ----
    {
        float4 sc = *(const float4*)(sscale + lane * 4);
        float4 bs = *(const float4*)(sbias + lane * 4);
        for (int d = wid; d < NNODE; d += 16) {
            int beg = sptr[d], end = sptr[d + 1];
            float rv = rinv[d];
            float4 acc = make_float4(0.f, 0.f, 0.f, 0.f);
            for (int p = beg; p < end; ++p) {
                float w = sex[p];
                const float4 v = *(const float4*)(sxh + scsr[p] * HFEAT + lane * 4);
                acc.x = fmaf(w, v.x, acc.x);
                acc.y = fmaf(w, v.y, acc.y);
                acc.z = fmaf(w, v.z, acc.z);
                acc.w = fmaf(w, v.w, acc.w);
            }
            float4 r;
            r.x = fmaxf(fmaf(acc.x * rv, sc.x, bs.x), 0.0f);
            r.y = fmaxf(fmaf(acc.y * rv, sc.y, bs.y), 0.0f);
            r.z = fmaxf(fmaf(acc.z * rv, sc.z, bs.z), 0.0f);
            r.w = fmaxf(fmaf(acc.w * rv, sc.w, bs.w), 0.0f);
            *(float4*)(sh + d * HFEAT + lane * 4) = r;
        }
    }
    __syncthreads();

    // ---- mean pool (pool aliases s_s/s_d region) ----
    {
        int g = tid >> 7, f = tid & 127;
        float acc = 0.0f;
#pragma unroll 4
        for (int n = g * 32; n < g * 32 + 32; ++n) acc += sh[n * HFEAT + f];
        pool[g * 128 + f] = acc;
    }
    __syncthreads();
    if (tid < 128)
        hp[tid] = (pool[tid] + pool[128 + tid] + pool[256 + tid] + pool[384 + tid])
                  * (1.0f / 128.0f);
    __syncthreads();

    // ---- MLP ----
    if (tid < 64) {
        float acc = b1[tid];
#pragma unroll 8
        for (int f = 0; f < 128; ++f) acc = fmaf(hp[f], w1[f * 64 + tid], acc);
        zz[tid] = fmaxf(acc, 0.0f);
    }
    __syncthreads();
    if (tid == 0) {
        float acc = b2[0];
#pragma unroll
        for (int j = 0; j < 64; ++j) acc = fmaf(zz[j], w2[j], acc);
        out[b] = acc;
    }
}

// ---------------------------------------------------------------------------
extern "C" void kernel_launch(void* const* d_in, const int* in_sizes, int n_in,
                              void* d_out, int out_size) {
    (void)in_sizes; (void)n_in; (void)out_size;
    const float* x    = (const float*)d_in[0];
    const int*   ei   = (const int*)d_in[1];
    const float* w_in = (const float*)d_in[2];
    const float* b_in = (const float*)d_in[3];
    const float* g0w  = (const float*)d_in[4];
    const float* g0as = (const float*)d_in[5];
    const float* g0ad = (const float*)d_in[6];
    const float* g0b  = (const float*)d_in[7];
    const float* bn0g = (const float*)d_in[8];
    const float* bn0b = (const float*)d_in[9];
    const float* bn0m = (const float*)d_in[10];
    const float* bn0v = (const float*)d_in[11];
    const float* g1w  = (const float*)d_in[12];
    const float* g1as = (const float*)d_in[13];
    const float* g1ad = (const float*)d_in[14];
    const float* g1b  = (const float*)d_in[15];
    const float* bn1g = (const float*)d_in[16];
    const float* bn1b = (const float*)d_in[17];
    const float* bn1m = (const float*)d_in[18];
    const float* bn1v = (const float*)d_in[19];
    const float* w1   = (const float*)d_in[20];
    const float* b1   = (const float*)d_in[21];
    const float* w2   = (const float*)d_in[22];
    const float* b2   = (const float*)d_in[23];
    float* out = (float*)d_out;

    cudaFuncSetAttribute(gnn_kernel,
                         cudaFuncAttributeMaxDynamicSharedMemorySize, SMEM_BYTES);

    setup_kernel<<<2, 1024>>>(ei, w_in, b_in, g0w);
    gnn_kernel<<<NGRAPH, NTHREADS, SMEM_BYTES>>>(
        x, g0as, g0ad, g0b, bn0g, bn0b, bn0m, bn0v,
        g1w, g1as, g1ad, g1b, bn1g, bn1b, bn1m, bn1v,
        w1, b1, w2, b2, out);
}